// round 2
// baseline (speedup 1.0000x reference)
#include <cuda_runtime.h>
#include <math.h>

// Problem constants
#define NB 8
#define RR 256
#define CI 64
#define CO 64
#define MODES 16
#define KX 32          // 2*MODES kx rows kept: {0..15} U {240..255}

// ---------------- device scratch (static, no allocs) ----------------
__device__ __align__(16) float g_Fx [64 * 256];          // [m][x]  m<32: cos, m>=32: -sin  (theta = 2*pi*kx*x/256)
__device__ __align__(16) float g_FxT[256 * 64];          // [x][m]  transpose for GEMM A
__device__ __align__(16) float g_Wy [256 * 16 * 2];      // [y][ky][{cos,sin}] theta = 2*pi*ky*y/256
__device__ __align__(16) float g_T  [NB * 64 * RR * CI]; // [b][m][y][c]   (33.5 MB)
__device__ __align__(16) float g_Gre[NB * KX * MODES * CI];
__device__ __align__(16) float g_Gim[NB * KX * MODES * CI];
__device__ __align__(16) float g_Hre[NB * CO * KX * MODES];
__device__ __align__(16) float g_Him[NB * CO * KX * MODES];
__device__ __align__(16) float g_Vre[NB * RR * CO * MODES]; // 8 MB
__device__ __align__(16) float g_Vim[NB * RR * CO * MODES]; // 8 MB

// ---------------- table init ----------------
__global__ void init_tables() {
    int t = blockIdx.x * blockDim.x + threadIdx.x;   // 0..16383
    if (t < 64 * 256) {
        int m = t >> 8, x = t & 255;
        int j = m & 31;
        int kx = (j < 16) ? j : (224 + j);           // j in [16,32) -> 240..255
        float s, c;
        sincospif((float)((kx * x) & 255) * (1.0f / 128.0f), &s, &c);
        float v = (m < 32) ? c : -s;
        g_Fx[m * 256 + x] = v;
        g_FxT[x * 64 + m] = v;
    }
    if (t < 256 * 16) {
        int y = t >> 4, ky = t & 15;
        float s, c;
        sincospif((float)((ky * y) & 255) * (1.0f / 128.0f), &s, &c);
        g_Wy[t * 2 + 0] = c;
        g_Wy[t * 2 + 1] = s;
    }
}

// ---------------- Stage A: x-direction partial DFT as GEMM ----------------
// T[b][m][yc] = sum_x FxT[x][m] * X[b][x][yc],  yc in [0,16384)
__global__ __launch_bounds__(256) void kA(const float* __restrict__ X) {
    int b  = blockIdx.y;
    int n0 = blockIdx.x * 64;
    __shared__ float As[32][64];
    __shared__ float Bs[32][64];
    const float* Xb = X + (size_t)b * RR * 16384;
    float* Tb = g_T + (size_t)b * 64 * 16384;
    int t  = threadIdx.x;
    int tn = (t & 15) * 4;
    int tm = (t >> 4) * 4;
    float acc[4][4] = {};
    for (int k0 = 0; k0 < 256; k0 += 32) {
        #pragma unroll
        for (int l = 0; l < 8; l++) {
            int e = t + l * 256;            // 0..2047
            int m = e & 63, k = e >> 6;
            As[k][m] = g_FxT[(k0 + k) * 64 + m];
        }
        #pragma unroll
        for (int l = 0; l < 2; l++) {
            int e = t + l * 256;            // float4 id 0..511
            int k = e >> 4, nv = (e & 15) * 4;
            *(float4*)&Bs[k][nv] =
                *(const float4*)&Xb[(size_t)(k0 + k) * 16384 + n0 + nv];
        }
        __syncthreads();
        #pragma unroll
        for (int k = 0; k < 32; k++) {
            float4 a4 = *(float4*)&As[k][tm];
            float4 b4 = *(float4*)&Bs[k][tn];
            acc[0][0] += a4.x * b4.x; acc[0][1] += a4.x * b4.y;
            acc[0][2] += a4.x * b4.z; acc[0][3] += a4.x * b4.w;
            acc[1][0] += a4.y * b4.x; acc[1][1] += a4.y * b4.y;
            acc[1][2] += a4.y * b4.z; acc[1][3] += a4.y * b4.w;
            acc[2][0] += a4.z * b4.x; acc[2][1] += a4.z * b4.y;
            acc[2][2] += a4.z * b4.z; acc[2][3] += a4.z * b4.w;
            acc[3][0] += a4.w * b4.x; acc[3][1] += a4.w * b4.y;
            acc[3][2] += a4.w * b4.z; acc[3][3] += a4.w * b4.w;
        }
        __syncthreads();
    }
    #pragma unroll
    for (int i = 0; i < 4; i++) {
        float4 v = make_float4(acc[i][0], acc[i][1], acc[i][2], acc[i][3]);
        *(float4*)&Tb[(size_t)(tm + i) * 16384 + n0 + tn] = v;
    }
}

// ---------------- Stage B: y-direction partial DFT (fold 1/256) ----------------
// G[b][j][ky][c] = (1/256) * sum_y (Tre + i Tim)[b][j][y][c] * e^{-i 2pi ky y / 256}
__global__ __launch_bounds__(256) void kB() {
    int j = blockIdx.x, b = blockIdx.y;
    __shared__ float Tre[32][64];
    __shared__ float Tim[32][64];
    __shared__ float Wys[256 * 16 * 2];   // 32KB
    int t = threadIdx.x;
    #pragma unroll
    for (int l = 0; l < 8; l++) {
        int e = (t + l * 256) * 4;        // float index, 8192 floats
        *(float4*)&Wys[e] = *(const float4*)&g_Wy[e];
    }
    const float* Tr = g_T + ((size_t)(b * 64 + j)      * 256) * 64;
    const float* Ti = g_T + ((size_t)(b * 64 + 32 + j) * 256) * 64;
    int c  = t & 63;
    int kg = t >> 6;                       // 0..3, handles ky = kg*4 + q
    float accR[4] = {}, accI[4] = {};
    for (int y0 = 0; y0 < 256; y0 += 32) {
        #pragma unroll
        for (int l = 0; l < 2; l++) {
            int e = t + l * 256;           // float4 id 0..511
            int yy = e >> 4, cv = (e & 15) * 4;
            *(float4*)&Tre[yy][cv] = *(const float4*)&Tr[(y0 + yy) * 64 + cv];
            *(float4*)&Tim[yy][cv] = *(const float4*)&Ti[(y0 + yy) * 64 + cv];
        }
        __syncthreads();
        for (int yy = 0; yy < 32; yy++) {
            float tr = Tre[yy][c], ti = Tim[yy][c];
            int y = y0 + yy;
            #pragma unroll
            for (int q = 0; q < 4; q++) {
                int ky = kg * 4 + q;
                float cc = Wys[(y * 16 + ky) * 2 + 0];
                float ss = Wys[(y * 16 + ky) * 2 + 1];
                accR[q] += tr * cc + ti * ss;   // (tr+i ti)*(c - i s)
                accI[q] += ti * cc - tr * ss;
            }
        }
        __syncthreads();
    }
    const float sc = 1.0f / 256.0f;
    #pragma unroll
    for (int q = 0; q < 4; q++) {
        int ky = kg * 4 + q;
        int idx = ((b * KX + j) * MODES + ky) * CI + c;
        g_Gre[idx] = accR[q] * sc;
        g_Gim[idx] = accI[q] * sc;
    }
}

// ---------------- Stage C: per-frequency complex channel mixing ----------------
// H[b][o][j][ky] = sum_i G[b][i] * w[i][o]   (complex)
__global__ __launch_bounds__(256) void kC(const float* __restrict__ fw0,
                                          const float* __restrict__ fw1) {
    int ky = blockIdx.x & 15, j = blockIdx.x >> 4;
    __shared__ float wr[64 * 64];
    __shared__ float wi[64 * 64];
    __shared__ float gr[8 * 64];
    __shared__ float gi[8 * 64];
    const float* fw = (j < 16) ? fw0 : fw1;
    int jm = j & 15;
    int t = threadIdx.x;
    #pragma unroll
    for (int l = 0; l < 16; l++) {
        int e = t + l * 256;               // 0..4095 : i = e>>6, o = e&63
        int i = e >> 6, o = e & 63;
        const float2 p = *(const float2*)&fw[((((size_t)i * 64 + o) * 16 + jm) * 16 + ky) * 2];
        wr[e] = p.x;
        wi[e] = p.y;
    }
    #pragma unroll
    for (int l = 0; l < 2; l++) {
        int e = t + l * 256;               // 0..511 : b = e>>6, i = e&63
        int b = e >> 6, i = e & 63;
        int gidx = ((b * KX + j) * MODES + ky) * CI + i;
        gr[e] = g_Gre[gidx];
        gi[e] = g_Gim[gidx];
    }
    __syncthreads();
    #pragma unroll
    for (int l = 0; l < 2; l++) {
        int p = t + l * 256;
        int b = p >> 6, o = p & 63;
        float hr = 0.f, hi = 0.f;
        #pragma unroll 8
        for (int i = 0; i < 64; i++) {
            float ar = gr[b * 64 + i], ai = gi[b * 64 + i];
            float br = wr[i * 64 + o], bi = wi[i * 64 + o];
            hr += ar * br - ai * bi;
            hi += ar * bi + ai * br;
        }
        int hidx = ((b * CO + o) * KX + j) * MODES + ky;
        g_Hre[hidx] = hr;
        g_Him[hidx] = hi;
    }
}

// ---------------- Stage D: inverse x-DFT (fold 1/256) ----------------
// V[b][x][o][ky] = (1/256) * sum_j H[b][o][j][ky] * e^{+i 2pi kx_j x / 256}
__global__ __launch_bounds__(256) void kD() {
    int o = blockIdx.x & 63, b = blockIdx.x >> 6;
    __shared__ __align__(16) float hr[KX * MODES];
    __shared__ __align__(16) float hi[KX * MODES];
    int t = threadIdx.x;
    int base = (b * CO + o) * KX * MODES;  // 512 per (b,o)
    hr[t]       = g_Hre[base + t];
    hi[t]       = g_Him[base + t];
    hr[t + 256] = g_Hre[base + t + 256];
    hi[t + 256] = g_Him[base + t + 256];
    __syncthreads();
    int x = t;
    float vr[16] = {}, vi[16] = {};
    for (int j = 0; j < 32; j++) {
        float c =  g_Fx[j * 256 + x];
        float s = -g_Fx[(32 + j) * 256 + x];
        #pragma unroll
        for (int kv = 0; kv < 4; kv++) {
            float4 ar = *(float4*)&hr[j * 16 + kv * 4];
            float4 ai = *(float4*)&hi[j * 16 + kv * 4];
            vr[kv*4+0] += ar.x * c - ai.x * s;  vi[kv*4+0] += ar.x * s + ai.x * c;
            vr[kv*4+1] += ar.y * c - ai.y * s;  vi[kv*4+1] += ar.y * s + ai.y * c;
            vr[kv*4+2] += ar.z * c - ai.z * s;  vi[kv*4+2] += ar.z * s + ai.z * c;
            vr[kv*4+3] += ar.w * c - ai.w * s;  vi[kv*4+3] += ar.w * s + ai.w * c;
        }
    }
    const float sc = 1.0f / 256.0f;
    size_t vbase = (((size_t)b * RR + x) * CO + o) * MODES;
    #pragma unroll
    for (int kv = 0; kv < 4; kv++) {
        float4 a = make_float4(vr[kv*4]*sc, vr[kv*4+1]*sc, vr[kv*4+2]*sc, vr[kv*4+3]*sc);
        float4 bb = make_float4(vi[kv*4]*sc, vi[kv*4+1]*sc, vi[kv*4+2]*sc, vi[kv*4+3]*sc);
        *(float4*)&g_Vre[vbase + kv * 4] = a;
        *(float4*)&g_Vim[vbase + kv * 4] = bb;
    }
}

// ---------------- Stage E: inverse y-DFT + residual GEMM + SiLU ----------------
// out[b][x][y][o] = silu( sum_ky f(ky)*(Vr*cos - Vi*sin) + b_res[o] + sum_i X[b][x][y][i]*W[i][o] )
__global__ __launch_bounds__(256) void kE(const float* __restrict__ X,
                                          const float* __restrict__ Wres,
                                          const float* __restrict__ bres,
                                          float* __restrict__ out) {
    int x = blockIdx.x & 255, b = blockIdx.x >> 8;
    __shared__ __align__(16) float Xs[128 * 64];   // 32KB, half-row chunk
    __shared__ __align__(16) float Ws[64 * 64];    // 16KB
    int t = threadIdx.x;
    #pragma unroll
    for (int l = 0; l < 16; l++) Ws[t + l * 256] = Wres[t + l * 256];

    int o  = t & 63;
    int yq = t >> 6;                               // 0..3
    // register-cache the W column for this thread's o
    float wv[64];
    float vr[16], vi[16];
    {
        size_t vbase = (((size_t)b * RR + x) * CO + o) * MODES;
        #pragma unroll
        for (int kv = 0; kv < 4; kv++) {
            float4 a = *(const float4*)&g_Vre[vbase + kv * 4];
            float4 c = *(const float4*)&g_Vim[vbase + kv * 4];
            vr[kv*4+0]=a.x; vr[kv*4+1]=a.y; vr[kv*4+2]=a.z; vr[kv*4+3]=a.w;
            vi[kv*4+0]=c.x; vi[kv*4+1]=c.y; vi[kv*4+2]=c.z; vi[kv*4+3]=c.w;
        }
    }
    float bv = bres[o];
    __syncthreads();
    #pragma unroll
    for (int i = 0; i < 64; i++) wv[i] = Ws[i * 64 + o];

    const float* Xrow = X   + ((size_t)(b * RR + x)) * 256 * 64;
    float*       orow = out + ((size_t)(b * RR + x)) * 256 * 64;

    for (int ch = 0; ch < 2; ch++) {
        int ybase = ch * 128;
        __syncthreads();
        #pragma unroll
        for (int l = 0; l < 8; l++) {
            int e = (t + l * 256) * 4;             // 8192 floats
            *(float4*)&Xs[e] = *(const float4*)&Xrow[ybase * 64 + e];
        }
        __syncthreads();
        for (int n = 0; n < 32; n++) {
            int yl = yq * 32 + n;                  // within chunk
            int y  = ybase + yl;
            // inverse y-DFT real part
            float inv = 0.f;
            #pragma unroll
            for (int ky = 0; ky < 16; ky++) {
                float2 cs = *(const float2*)&g_Wy[(y * 16 + ky) * 2];
                float f = (ky == 0) ? 1.0f : 2.0f;
                inv += f * (vr[ky] * cs.x - vi[ky] * cs.y);
            }
            // residual matvec
            float acc = bv;
            #pragma unroll
            for (int i = 0; i < 64; i += 4) {
                float4 xv = *(float4*)&Xs[yl * 64 + i];
                acc += xv.x * wv[i] + xv.y * wv[i+1] + xv.z * wv[i+2] + xv.w * wv[i+3];
            }
            float v = acc + inv;
            float sig = 1.0f / (1.0f + __expf(-v));
            orow[y * 64 + o] = v * sig;
        }
    }
}

// ---------------- launch ----------------
extern "C" void kernel_launch(void* const* d_in, const int* in_sizes, int n_in,
                              void* d_out, int out_size) {
    const float* X    = (const float*)d_in[0];
    const float* Wres = (const float*)d_in[1];
    const float* bres = (const float*)d_in[2];
    const float* fw0  = (const float*)d_in[3];
    const float* fw1  = (const float*)d_in[4];
    float* out = (float*)d_out;

    init_tables<<<64, 256>>>();
    kA<<<dim3(256, NB), 256>>>(X);
    kB<<<dim3(KX, NB), 256>>>();
    kC<<<KX * MODES, 256>>>(fw0, fw1);
    kD<<<NB * CO, 256>>>();
    kE<<<NB * RR, 256>>>(X, Wres, bres, out);
}

// round 3
// speedup vs baseline: 1.2384x; 1.2384x over previous
#include <cuda_runtime.h>
#include <math.h>

#define NB 8
#define RR 256
#define CI 64
#define CO 64
#define MODES 16
#define KX 32

// ---------------- f32x2 helpers ----------------
__device__ __forceinline__ unsigned long long f2pack(float a, float b) {
    unsigned long long r;
    asm("mov.b64 %0, {%1, %2};" : "=l"(r) : "f"(a), "f"(b));
    return r;
}
__device__ __forceinline__ void f2unpack(unsigned long long v, float& a, float& b) {
    asm("mov.b64 {%0, %1}, %2;" : "=f"(a), "=f"(b) : "l"(v));
}
__device__ __forceinline__ void ffma2(unsigned long long& d, unsigned long long a,
                                      unsigned long long b) {
    asm("fma.rn.f32x2 %0, %1, %2, %3;" : "=l"(d) : "l"(a), "l"(b), "l"(d));
}

// ---------------- device scratch ----------------
__device__ __align__(16) float g_Fx [64 * 256];       // [m][x] m<32:cos m>=32:-sin (kD)
__device__ __align__(16) float g_FxB[256 * 96];       // [x][m'] m'<32:cos 32..63:+sin 64..95:-sin (kB2)
__device__ __align__(16) float g_Wy2[256 * 32];       // [y][kk] kk<16:cos kk>=16:-sin (kA2)
__device__ __align__(16) float g_WyE[32 * 256];       // [k'][y] k'<16: f*cos ; k'>=16: -f*sin (kE)
__device__ __align__(16) float g_T  [2 * 2097152];    // G1re | G1im : [b][ky][x][c]
__device__ __align__(16) float g_Gre[NB * KX * MODES * CI];
__device__ __align__(16) float g_Gim[NB * KX * MODES * CI];
__device__ __align__(16) float g_Hre[NB * CO * KX * MODES];
__device__ __align__(16) float g_Him[NB * CO * KX * MODES];
__device__ __align__(16) float g_Vre[NB * RR * MODES * CO];  // [b][x][ky][o]
__device__ __align__(16) float g_Vim[NB * RR * MODES * CO];

// ---------------- table init ----------------
__global__ void init_tables() {
    int t = blockIdx.x * blockDim.x + threadIdx.x;   // < 24576
    if (t < 64 * 256) {                               // g_Fx
        int m = t >> 8, x = t & 255;
        int j = m & 31;
        int kx = (j < 16) ? j : (224 + j);
        float s, c;
        sincospif((float)((kx * x) & 255) * (1.0f / 128.0f), &s, &c);
        g_Fx[t] = (m < 32) ? c : -s;
    }
    if (t < 256 * 96) {                               // g_FxB
        int x = t / 96, m = t % 96;
        int j = m & 31;
        int kx = (j < 16) ? j : (224 + j);
        float s, c;
        sincospif((float)((kx * x) & 255) * (1.0f / 128.0f), &s, &c);
        g_FxB[t] = (m < 32) ? c : ((m < 64) ? s : -s);
    }
    if (t < 256 * 32) {                               // g_Wy2
        int y = t >> 5, kk = t & 31;
        int ky = kk & 15;
        float s, c;
        sincospif((float)((ky * y) & 255) * (1.0f / 128.0f), &s, &c);
        g_Wy2[t] = (kk < 16) ? c : -s;
    }
    if (t < 32 * 256) {                               // g_WyE
        int kk = t >> 8, y = t & 255;
        int ky = kk & 15;
        float f = (ky == 0) ? 1.0f : 2.0f;
        float s, c;
        sincospif((float)((ky * y) & 255) * (1.0f / 128.0f), &s, &c);
        g_WyE[t] = (kk < 16) ? f * c : -f * s;
    }
}

// ---------------- Stage A': y-direction partial DFT ----------------
// G1[b][ky][x][c] (re,im) = sum_y X[b][x][y][c] * e^{-i 2pi ky y/256}
__global__ __launch_bounds__(256) void kA2(const float* __restrict__ X) {
    int b  = blockIdx.y;
    int x0 = blockIdx.x * 4;
    __shared__ __align__(16) float Xs[4][32][64];   // 32KB
    __shared__ __align__(16) float Wys[32][32];     // 4KB
    int t  = threadIdx.x;
    int xl = t >> 6;
    int tt = t & 63;
    int kg = tt >> 3;            // kk = kg*4
    int cg = tt & 7;             // c  = cg*8
    int kk0 = kg * 4, c0 = cg * 8;

    unsigned long long acc[4][4];
    #pragma unroll
    for (int i = 0; i < 4; i++)
        #pragma unroll
        for (int p = 0; p < 4; p++) acc[i][p] = 0ull;

    for (int ych = 0; ych < 8; ych++) {
        int y0 = ych * 32;
        #pragma unroll
        for (int l = 0; l < 8; l++) {
            int e = t + l * 256;             // float4 id 0..2047
            int c4 = e & 15, yy = (e >> 4) & 31, xs = e >> 9;
            *(float4*)&Xs[xs][yy][c4 * 4] =
                *(const float4*)&X[((size_t)((b * 256 + x0 + xs)) * 256 + y0 + yy) * 64 + c4 * 4];
        }
        {
            int kk4 = t & 7, yy = t >> 3;
            *(float4*)&Wys[yy][kk4 * 4] = *(const float4*)&g_Wy2[(y0 + yy) * 32 + kk4 * 4];
        }
        __syncthreads();
        #pragma unroll 8
        for (int yy = 0; yy < 32; yy++) {
            float4 a4 = *(float4*)&Wys[yy][kk0];
            unsigned long long pa0 = f2pack(a4.x, a4.x);
            unsigned long long pa1 = f2pack(a4.y, a4.y);
            unsigned long long pa2 = f2pack(a4.z, a4.z);
            unsigned long long pa3 = f2pack(a4.w, a4.w);
            ulonglong2 b01 = *(ulonglong2*)&Xs[xl][yy][c0];
            ulonglong2 b23 = *(ulonglong2*)&Xs[xl][yy][c0 + 4];
            ffma2(acc[0][0], pa0, b01.x); ffma2(acc[0][1], pa0, b01.y);
            ffma2(acc[0][2], pa0, b23.x); ffma2(acc[0][3], pa0, b23.y);
            ffma2(acc[1][0], pa1, b01.x); ffma2(acc[1][1], pa1, b01.y);
            ffma2(acc[1][2], pa1, b23.x); ffma2(acc[1][3], pa1, b23.y);
            ffma2(acc[2][0], pa2, b01.x); ffma2(acc[2][1], pa2, b01.y);
            ffma2(acc[2][2], pa2, b23.x); ffma2(acc[2][3], pa2, b23.y);
            ffma2(acc[3][0], pa3, b01.x); ffma2(acc[3][1], pa3, b01.y);
            ffma2(acc[3][2], pa3, b23.x); ffma2(acc[3][3], pa3, b23.y);
        }
        __syncthreads();
    }
    int x = x0 + xl;
    #pragma unroll
    for (int j = 0; j < 4; j++) {
        int kk = kk0 + j;
        int ky = kk & 15;
        float* dst = (kk < 16 ? g_T : g_T + 2097152) +
                     ((size_t)((b * 16 + ky) * 256 + x)) * 64 + c0;
        float v[8];
        #pragma unroll
        for (int p = 0; p < 4; p++) f2unpack(acc[j][p], v[2 * p], v[2 * p + 1]);
        *(float4*)&dst[0] = make_float4(v[0], v[1], v[2], v[3]);
        *(float4*)&dst[4] = make_float4(v[4], v[5], v[6], v[7]);
    }
}

// ---------------- Stage B': x-direction partial DFT (complex, fold 1/256) ----------------
__global__ __launch_bounds__(128) void kB2() {
    int b = blockIdx.x >> 4, ky = blockIdx.x & 15;
    __shared__ __align__(16) float Gr[32 * 64];
    __shared__ __align__(16) float Gi[32 * 64];
    __shared__ __align__(16) float Fxs[32 * 96];
    int t = threadIdx.x;                 // 0..127
    int jg = t >> 4, cg = t & 15;
    int j0 = jg * 4, c0 = cg * 4;

    const float* G1r = g_T + ((size_t)(b * 16 + ky)) * 256 * 64;
    const float* G1i = g_T + 2097152 + ((size_t)(b * 16 + ky)) * 256 * 64;

    unsigned long long aR[4][2], aI[4][2];
    #pragma unroll
    for (int i = 0; i < 4; i++) { aR[i][0]=aR[i][1]=aI[i][0]=aI[i][1]=0ull; }

    for (int x0 = 0; x0 < 256; x0 += 32) {
        #pragma unroll
        for (int l = 0; l < 4; l++) {
            int e = t + l * 128;         // f4 id 0..511 over 2048 floats
            ((float4*)Gr)[e] = ((const float4*)(G1r + (size_t)x0 * 64))[e];
            ((float4*)Gi)[e] = ((const float4*)(G1i + (size_t)x0 * 64))[e];
        }
        #pragma unroll
        for (int l = 0; l < 6; l++) {
            int e = t + l * 128;         // f4 id 0..767 over 3072 floats
            ((float4*)Fxs)[e] = ((const float4*)(g_FxB + (size_t)x0 * 96))[e];
        }
        __syncthreads();
        #pragma unroll 4
        for (int xx = 0; xx < 32; xx++) {
            float4 cv = *(float4*)&Fxs[xx * 96 + j0];
            float4 sv = *(float4*)&Fxs[xx * 96 + 32 + j0];
            float4 sn = *(float4*)&Fxs[xx * 96 + 64 + j0];
            ulonglong2 grp = *(ulonglong2*)&Gr[xx * 64 + c0];
            ulonglong2 gip = *(ulonglong2*)&Gi[xx * 64 + c0];
            unsigned long long pc[4] = {f2pack(cv.x,cv.x), f2pack(cv.y,cv.y),
                                        f2pack(cv.z,cv.z), f2pack(cv.w,cv.w)};
            unsigned long long ps[4] = {f2pack(sv.x,sv.x), f2pack(sv.y,sv.y),
                                        f2pack(sv.z,sv.z), f2pack(sv.w,sv.w)};
            unsigned long long pn[4] = {f2pack(sn.x,sn.x), f2pack(sn.y,sn.y),
                                        f2pack(sn.z,sn.z), f2pack(sn.w,sn.w)};
            #pragma unroll
            for (int jj = 0; jj < 4; jj++) {
                ffma2(aR[jj][0], pc[jj], grp.x); ffma2(aR[jj][0], ps[jj], gip.x);
                ffma2(aR[jj][1], pc[jj], grp.y); ffma2(aR[jj][1], ps[jj], gip.y);
                ffma2(aI[jj][0], pc[jj], gip.x); ffma2(aI[jj][0], pn[jj], grp.x);
                ffma2(aI[jj][1], pc[jj], gip.y); ffma2(aI[jj][1], pn[jj], grp.y);
            }
        }
        __syncthreads();
    }
    const float sc = 1.0f / 256.0f;
    #pragma unroll
    for (int jj = 0; jj < 4; jj++) {
        int j = j0 + jj;
        int idx = ((b * KX + j) * MODES + ky) * CI + c0;
        float r0, r1, r2, r3, i0, i1, i2, i3;
        f2unpack(aR[jj][0], r0, r1); f2unpack(aR[jj][1], r2, r3);
        f2unpack(aI[jj][0], i0, i1); f2unpack(aI[jj][1], i2, i3);
        *(float4*)&g_Gre[idx] = make_float4(r0*sc, r1*sc, r2*sc, r3*sc);
        *(float4*)&g_Gim[idx] = make_float4(i0*sc, i1*sc, i2*sc, i3*sc);
    }
}

// ---------------- Stage C: per-frequency complex channel mixing (unchanged) ----------------
__global__ __launch_bounds__(256) void kC(const float* __restrict__ fw0,
                                          const float* __restrict__ fw1) {
    int ky = blockIdx.x & 15, j = blockIdx.x >> 4;
    __shared__ float wr[64 * 64];
    __shared__ float wi[64 * 64];
    __shared__ float gr[8 * 64];
    __shared__ float gi[8 * 64];
    const float* fw = (j < 16) ? fw0 : fw1;
    int jm = j & 15;
    int t = threadIdx.x;
    #pragma unroll
    for (int l = 0; l < 16; l++) {
        int e = t + l * 256;
        int i = e >> 6, o = e & 63;
        const float2 p = *(const float2*)&fw[((((size_t)i * 64 + o) * 16 + jm) * 16 + ky) * 2];
        wr[e] = p.x;
        wi[e] = p.y;
    }
    #pragma unroll
    for (int l = 0; l < 2; l++) {
        int e = t + l * 256;
        int b = e >> 6, i = e & 63;
        int gidx = ((b * KX + j) * MODES + ky) * CI + i;
        gr[e] = g_Gre[gidx];
        gi[e] = g_Gim[gidx];
    }
    __syncthreads();
    #pragma unroll
    for (int l = 0; l < 2; l++) {
        int p = t + l * 256;
        int b = p >> 6, o = p & 63;
        float hr = 0.f, hi = 0.f;
        #pragma unroll 8
        for (int i = 0; i < 64; i++) {
            float ar = gr[b * 64 + i], ai = gi[b * 64 + i];
            float br = wr[i * 64 + o], bi = wi[i * 64 + o];
            hr += ar * br - ai * bi;
            hi += ar * bi + ai * br;
        }
        int hidx = ((b * CO + o) * KX + j) * MODES + ky;
        g_Hre[hidx] = hr;
        g_Him[hidx] = hi;
    }
}

// ---------------- Stage D: inverse x-DFT (fold 1/256), layout [b][x][ky][o] ----------------
__global__ __launch_bounds__(256) void kD() {
    int o = blockIdx.x & 63, b = blockIdx.x >> 6;
    __shared__ __align__(16) float hr[KX * MODES];
    __shared__ __align__(16) float hi[KX * MODES];
    int t = threadIdx.x;
    int base = (b * CO + o) * KX * MODES;
    hr[t]       = g_Hre[base + t];
    hi[t]       = g_Him[base + t];
    hr[t + 256] = g_Hre[base + t + 256];
    hi[t + 256] = g_Him[base + t + 256];
    __syncthreads();
    int x = t;
    float vr[16] = {}, vi[16] = {};
    for (int j = 0; j < 32; j++) {
        float c =  g_Fx[j * 256 + x];
        float s = -g_Fx[(32 + j) * 256 + x];
        #pragma unroll
        for (int kv = 0; kv < 4; kv++) {
            float4 ar = *(float4*)&hr[j * 16 + kv * 4];
            float4 ai = *(float4*)&hi[j * 16 + kv * 4];
            vr[kv*4+0] += ar.x * c - ai.x * s;  vi[kv*4+0] += ar.x * s + ai.x * c;
            vr[kv*4+1] += ar.y * c - ai.y * s;  vi[kv*4+1] += ar.y * s + ai.y * c;
            vr[kv*4+2] += ar.z * c - ai.z * s;  vi[kv*4+2] += ar.z * s + ai.z * c;
            vr[kv*4+3] += ar.w * c - ai.w * s;  vi[kv*4+3] += ar.w * s + ai.w * c;
        }
    }
    const float sc = 1.0f / 256.0f;
    size_t vbase = ((size_t)(b * 256 + x)) * 16 * 64 + o;
    #pragma unroll
    for (int ky = 0; ky < 16; ky++) {
        g_Vre[vbase + ky * 64] = vr[ky] * sc;
        g_Vim[vbase + ky * 64] = vi[ky] * sc;
    }
}

// ---------------- Stage E: unified K=96 GEMM (residual + inverse-y) + SiLU ----------------
// out[y][o] = silu( sum_{k<64} X[y][k]*W[k][o] + sum_{k'<32} WyE[k'][y]*V'[k'][o] + b[o] )
__global__ __launch_bounds__(256) void kE(const float* __restrict__ X,
                                          const float* __restrict__ Wres,
                                          const float* __restrict__ bres,
                                          float* __restrict__ out) {
    extern __shared__ float sm[];
    float* As2  = sm;                    // [128][68]
    float* Bs   = sm + 128 * 68;         // [96][64]
    float* Tbs  = Bs + 96 * 64;          // [32][128]
    float* bias = Tbs + 32 * 128;        // [64]

    int bi = blockIdx.x;
    int b = bi >> 8, x = bi & 255;
    int t = threadIdx.x;
    int og = t & 7, yg = t >> 3;
    int o = og * 8;
    int ybase = yg * 4;

    // stage B side once
    #pragma unroll
    for (int l = 0; l < 4; l++) {
        int e = t + l * 256;
        ((float4*)Bs)[e] = ((const float4*)Wres)[e];
    }
    {
        size_t vb = ((size_t)(b * 256 + x)) * 1024;
        ((float4*)(Bs + 4096))[t] = ((const float4*)(g_Vre + vb))[t];
        ((float4*)(Bs + 5120))[t] = ((const float4*)(g_Vim + vb))[t];
    }
    if (t < 64) bias[t] = bres[t];

    const float* Xrow = X   + ((size_t)(b * 256 + x)) * 256 * 64;
    float*       orow = out + ((size_t)(b * 256 + x)) * 256 * 64;

    for (int ch = 0; ch < 2; ch++) {
        int y0 = ch * 128;
        __syncthreads();
        #pragma unroll
        for (int l = 0; l < 8; l++) {
            int e = t + l * 256;             // f4 id 0..2047
            int i4 = e & 15, yy = e >> 4;
            *(float4*)&As2[yy * 68 + i4 * 4] =
                *(const float4*)&Xrow[(size_t)(y0 + yy) * 64 + i4 * 4];
        }
        #pragma unroll
        for (int l = 0; l < 4; l++) {
            int e = t + l * 256;             // f4 id 0..1023
            int kk = e >> 5, y4 = e & 31;
            *(float4*)&Tbs[kk * 128 + y4 * 4] =
                *(const float4*)&g_WyE[kk * 256 + y0 + y4 * 4];
        }
        __syncthreads();

        unsigned long long acc[4][4];
        #pragma unroll
        for (int r = 0; r < 4; r++)
            #pragma unroll
            for (int p = 0; p < 4; p++) acc[r][p] = 0ull;

        #pragma unroll 8
        for (int k = 0; k < 64; k++) {
            float a0 = As2[(ybase + 0) * 68 + k];
            float a1 = As2[(ybase + 1) * 68 + k];
            float a2 = As2[(ybase + 2) * 68 + k];
            float a3 = As2[(ybase + 3) * 68 + k];
            unsigned long long p0 = f2pack(a0, a0), p1 = f2pack(a1, a1);
            unsigned long long p2 = f2pack(a2, a2), p3 = f2pack(a3, a3);
            ulonglong2 b01 = *(ulonglong2*)&Bs[k * 64 + o];
            ulonglong2 b23 = *(ulonglong2*)&Bs[k * 64 + o + 4];
            ffma2(acc[0][0], p0, b01.x); ffma2(acc[0][1], p0, b01.y);
            ffma2(acc[0][2], p0, b23.x); ffma2(acc[0][3], p0, b23.y);
            ffma2(acc[1][0], p1, b01.x); ffma2(acc[1][1], p1, b01.y);
            ffma2(acc[1][2], p1, b23.x); ffma2(acc[1][3], p1, b23.y);
            ffma2(acc[2][0], p2, b01.x); ffma2(acc[2][1], p2, b01.y);
            ffma2(acc[2][2], p2, b23.x); ffma2(acc[2][3], p2, b23.y);
            ffma2(acc[3][0], p3, b01.x); ffma2(acc[3][1], p3, b01.y);
            ffma2(acc[3][2], p3, b23.x); ffma2(acc[3][3], p3, b23.y);
        }
        #pragma unroll 8
        for (int kk = 0; kk < 32; kk++) {
            float4 a4 = *(float4*)&Tbs[kk * 128 + ybase];
            unsigned long long p0 = f2pack(a4.x, a4.x), p1 = f2pack(a4.y, a4.y);
            unsigned long long p2 = f2pack(a4.z, a4.z), p3 = f2pack(a4.w, a4.w);
            ulonglong2 b01 = *(ulonglong2*)&Bs[(64 + kk) * 64 + o];
            ulonglong2 b23 = *(ulonglong2*)&Bs[(64 + kk) * 64 + o + 4];
            ffma2(acc[0][0], p0, b01.x); ffma2(acc[0][1], p0, b01.y);
            ffma2(acc[0][2], p0, b23.x); ffma2(acc[0][3], p0, b23.y);
            ffma2(acc[1][0], p1, b01.x); ffma2(acc[1][1], p1, b01.y);
            ffma2(acc[1][2], p1, b23.x); ffma2(acc[1][3], p1, b23.y);
            ffma2(acc[2][0], p2, b01.x); ffma2(acc[2][1], p2, b01.y);
            ffma2(acc[2][2], p2, b23.x); ffma2(acc[2][3], p2, b23.y);
            ffma2(acc[3][0], p3, b01.x); ffma2(acc[3][1], p3, b01.y);
            ffma2(acc[3][2], p3, b23.x); ffma2(acc[3][3], p3, b23.y);
        }
        // epilogue
        #pragma unroll
        for (int r = 0; r < 4; r++) {
            int y = y0 + ybase + r;
            float v[8];
            #pragma unroll
            for (int p = 0; p < 4; p++) f2unpack(acc[r][p], v[2 * p], v[2 * p + 1]);
            #pragma unroll
            for (int q = 0; q < 8; q++) {
                float z = v[q] + bias[o + q];
                v[q] = z / (1.0f + __expf(-z));
            }
            *(float4*)&orow[(size_t)y * 64 + o]     = make_float4(v[0], v[1], v[2], v[3]);
            *(float4*)&orow[(size_t)y * 64 + o + 4] = make_float4(v[4], v[5], v[6], v[7]);
        }
    }
}

// ---------------- launch ----------------
extern "C" void kernel_launch(void* const* d_in, const int* in_sizes, int n_in,
                              void* d_out, int out_size) {
    const float* X    = (const float*)d_in[0];
    const float* Wres = (const float*)d_in[1];
    const float* bres = (const float*)d_in[2];
    const float* fw0  = (const float*)d_in[3];
    const float* fw1  = (const float*)d_in[4];
    float* out = (float*)d_out;

    const int kE_smem = (128 * 68 + 96 * 64 + 32 * 128 + 64) * 4;
    static int attr_done = 0;
    if (!attr_done) {
        cudaFuncSetAttribute(kE, cudaFuncAttributeMaxDynamicSharedMemorySize, kE_smem);
        attr_done = 1;
    }

    init_tables<<<96, 256>>>();
    kA2<<<dim3(64, NB), 256>>>(X);
    kB2<<<128, 128>>>();
    kC<<<KX * MODES, 256>>>(fw0, fw1);
    kD<<<NB * CO, 256>>>();
    kE<<<NB * RR, 256, kE_smem>>>(X, Wres, bres, out);
}

// round 5
// speedup vs baseline: 1.2661x; 1.0224x over previous
#include <cuda_runtime.h>
#include <math.h>
#include <stdint.h>

#define NB 8
#define RR 256
#define CI 64
#define CO 64
#define MODES 16
#define KX 32

// ---------------- f32x2 helpers ----------------
__device__ __forceinline__ unsigned long long f2pack(float a, float b) {
    unsigned long long r;
    asm("mov.b64 %0, {%1, %2};" : "=l"(r) : "f"(a), "f"(b));
    return r;
}
__device__ __forceinline__ void f2unpack(unsigned long long v, float& a, float& b) {
    asm("mov.b64 {%0, %1}, %2;" : "=f"(a), "=f"(b) : "l"(v));
}
__device__ __forceinline__ void ffma2(unsigned long long& d, unsigned long long a,
                                      unsigned long long b) {
    asm("fma.rn.f32x2 %0, %1, %2, %3;" : "=l"(d) : "l"(a), "l"(b), "l"(d));
}

// ---------------- tf32 helpers ----------------
__device__ __forceinline__ float tf32f(float f) {
    uint32_t r;
    asm("cvt.rna.tf32.f32 %0, %1;" : "=r"(r) : "f"(f));
    return __uint_as_float(r);
}
__device__ __forceinline__ void mma_tf32(float& c0, float& c1, float& c2, float& c3,
                                         uint32_t a0, uint32_t a1, uint32_t a2, uint32_t a3,
                                         uint32_t b0, uint32_t b1) {
    asm("mma.sync.aligned.m16n8k8.row.col.f32.tf32.tf32.f32 "
        "{%0,%1,%2,%3}, {%4,%5,%6,%7}, {%8,%9}, {%0,%1,%2,%3};"
        : "+f"(c0), "+f"(c1), "+f"(c2), "+f"(c3)
        : "r"(a0), "r"(a1), "r"(a2), "r"(a3), "r"(b0), "r"(b1));
}

// ---------------- device scratch ----------------
__device__ __align__(16) float g_Fx [64 * 256];       // [m][x] m<32:cos m>=32:-sin (kD)
__device__ __align__(16) float g_FxB[256 * 96];       // [x][m'] (kB2)
__device__ __align__(16) float g_Wy2[256 * 32];       // [y][kk] (kA2)
__device__ __align__(16) float g_WyE[32 * 256];       // [k'][y] (kE)
__device__ __align__(16) float g_T  [2 * 2097152];    // G1re | G1im : [b][ky][x][c]
__device__ __align__(16) float g_Gre[NB * KX * MODES * CI];
__device__ __align__(16) float g_Gim[NB * KX * MODES * CI];
__device__ __align__(16) float g_Hre[NB * CO * KX * MODES];
__device__ __align__(16) float g_Him[NB * CO * KX * MODES];
__device__ __align__(16) float g_Vre[NB * RR * MODES * CO];  // [b][x][ky][o]
__device__ __align__(16) float g_Vim[NB * RR * MODES * CO];
__device__ __align__(16) float g_Wr [KX * MODES * CI * CO];  // [j][ky][i][o]
__device__ __align__(16) float g_Wi [KX * MODES * CI * CO];

// ---------------- table init ----------------
__global__ void init_tables() {
    int t = blockIdx.x * blockDim.x + threadIdx.x;   // < 24576
    if (t < 64 * 256) {                               // g_Fx
        int m = t >> 8, x = t & 255;
        int j = m & 31;
        int kx = (j < 16) ? j : (224 + j);
        float s, c;
        sincospif((float)((kx * x) & 255) * (1.0f / 128.0f), &s, &c);
        g_Fx[t] = (m < 32) ? c : -s;
    }
    if (t < 256 * 96) {                               // g_FxB
        int x = t / 96, m = t % 96;
        int j = m & 31;
        int kx = (j < 16) ? j : (224 + j);
        float s, c;
        sincospif((float)((kx * x) & 255) * (1.0f / 128.0f), &s, &c);
        g_FxB[t] = (m < 32) ? c : ((m < 64) ? s : -s);
    }
    if (t < 256 * 32) {                               // g_Wy2
        int y = t >> 5, kk = t & 31;
        int ky = kk & 15;
        float s, c;
        sincospif((float)((ky * y) & 255) * (1.0f / 128.0f), &s, &c);
        g_Wy2[t] = (kk < 16) ? c : -s;
    }
    if (t < 32 * 256) {                               // g_WyE
        int kk = t >> 8, y = t & 255;
        int ky = kk & 15;
        float f = (ky == 0) ? 1.0f : 2.0f;
        float s, c;
        sincospif((float)((ky * y) & 255) * (1.0f / 128.0f), &s, &c);
        g_WyE[t] = (kk < 16) ? f * c : -f * s;
    }
}

// ---------------- kW: transpose spectral weights to [j][ky][i][o] ----------------
// grid: 512 blocks = i(64) x og(8). Each block handles 8 o values for one i.
__global__ __launch_bounds__(256) void kW(const float* __restrict__ fw0,
                                          const float* __restrict__ fw1) {
    __shared__ float s[8 * 512];
    int i = blockIdx.x >> 3, og = blockIdx.x & 7;
    int o0 = og * 8;
    int t = threadIdx.x;
    for (int sel = 0; sel < 2; sel++) {
        const float* fw = sel ? fw1 : fw0;
        __syncthreads();
        #pragma unroll
        for (int l = 0; l < 4; l++) {
            int e = t + l * 256;             // f4 id 0..1023 (4096 floats)
            int o = e >> 7, rem = e & 127;   // 512 floats per o row
            ((float4*)s)[o * 128 + rem] =
                ((const float4*)(fw + ((size_t)(i * 64 + o0 + o)) * 512))[rem];
        }
        __syncthreads();
        #pragma unroll
        for (int l = 0; l < 8; l++) {
            int e = t + l * 256;             // 0..2047 : o = e&7, jk = e>>3 in [0,256)
            int o = e & 7, jk = e >> 3;      // jk = jm*16+ky
            int j = sel * 16 + (jk >> 4);
            int ky = jk & 15;
            int outi = ((j * 16 + ky) * 64 + i) * 64 + o0 + o;
            g_Wr[outi] = s[o * 512 + jk * 2];
            g_Wi[outi] = s[o * 512 + jk * 2 + 1];
        }
    }
}

// ---------------- Stage A': y-direction partial DFT ----------------
__global__ __launch_bounds__(256) void kA2(const float* __restrict__ X) {
    int b  = blockIdx.y;
    int x0 = blockIdx.x * 4;
    __shared__ __align__(16) float Xs[4][32][64];
    __shared__ __align__(16) float Wys[32][32];
    int t  = threadIdx.x;
    int xl = t >> 6;
    int tt = t & 63;
    int kg = tt >> 3;
    int cg = tt & 7;
    int kk0 = kg * 4, c0 = cg * 8;

    unsigned long long acc[4][4];
    #pragma unroll
    for (int i = 0; i < 4; i++)
        #pragma unroll
        for (int p = 0; p < 4; p++) acc[i][p] = 0ull;

    for (int ych = 0; ych < 8; ych++) {
        int y0 = ych * 32;
        #pragma unroll
        for (int l = 0; l < 8; l++) {
            int e = t + l * 256;
            int c4 = e & 15, yy = (e >> 4) & 31, xs = e >> 9;
            *(float4*)&Xs[xs][yy][c4 * 4] =
                *(const float4*)&X[((size_t)((b * 256 + x0 + xs)) * 256 + y0 + yy) * 64 + c4 * 4];
        }
        {
            int kk4 = t & 7, yy = t >> 3;
            *(float4*)&Wys[yy][kk4 * 4] = *(const float4*)&g_Wy2[(y0 + yy) * 32 + kk4 * 4];
        }
        __syncthreads();
        #pragma unroll 8
        for (int yy = 0; yy < 32; yy++) {
            float4 a4 = *(float4*)&Wys[yy][kk0];
            unsigned long long pa0 = f2pack(a4.x, a4.x);
            unsigned long long pa1 = f2pack(a4.y, a4.y);
            unsigned long long pa2 = f2pack(a4.z, a4.z);
            unsigned long long pa3 = f2pack(a4.w, a4.w);
            ulonglong2 b01 = *(ulonglong2*)&Xs[xl][yy][c0];
            ulonglong2 b23 = *(ulonglong2*)&Xs[xl][yy][c0 + 4];
            ffma2(acc[0][0], pa0, b01.x); ffma2(acc[0][1], pa0, b01.y);
            ffma2(acc[0][2], pa0, b23.x); ffma2(acc[0][3], pa0, b23.y);
            ffma2(acc[1][0], pa1, b01.x); ffma2(acc[1][1], pa1, b01.y);
            ffma2(acc[1][2], pa1, b23.x); ffma2(acc[1][3], pa1, b23.y);
            ffma2(acc[2][0], pa2, b01.x); ffma2(acc[2][1], pa2, b01.y);
            ffma2(acc[2][2], pa2, b23.x); ffma2(acc[2][3], pa2, b23.y);
            ffma2(acc[3][0], pa3, b01.x); ffma2(acc[3][1], pa3, b01.y);
            ffma2(acc[3][2], pa3, b23.x); ffma2(acc[3][3], pa3, b23.y);
        }
        __syncthreads();
    }
    int x = x0 + xl;
    #pragma unroll
    for (int j = 0; j < 4; j++) {
        int kk = kk0 + j;
        int ky = kk & 15;
        float* dst = (kk < 16 ? g_T : g_T + 2097152) +
                     ((size_t)((b * 16 + ky) * 256 + x)) * 64 + c0;
        float v[8];
        #pragma unroll
        for (int p = 0; p < 4; p++) f2unpack(acc[j][p], v[2 * p], v[2 * p + 1]);
        *(float4*)&dst[0] = make_float4(v[0], v[1], v[2], v[3]);
        *(float4*)&dst[4] = make_float4(v[4], v[5], v[6], v[7]);
    }
}

// ---------------- Stage B': x-direction partial DFT (complex, fold 1/256) ----------------
__global__ __launch_bounds__(128) void kB2() {
    int b = blockIdx.x >> 4, ky = blockIdx.x & 15;
    __shared__ __align__(16) float Gr[32 * 64];
    __shared__ __align__(16) float Gi[32 * 64];
    __shared__ __align__(16) float Fxs[32 * 96];
    int t = threadIdx.x;
    int jg = t >> 4, cg = t & 15;
    int j0 = jg * 4, c0 = cg * 4;

    const float* G1r = g_T + ((size_t)(b * 16 + ky)) * 256 * 64;
    const float* G1i = g_T + 2097152 + ((size_t)(b * 16 + ky)) * 256 * 64;

    unsigned long long aR[4][2], aI[4][2];
    #pragma unroll
    for (int i = 0; i < 4; i++) { aR[i][0]=aR[i][1]=aI[i][0]=aI[i][1]=0ull; }

    for (int x0 = 0; x0 < 256; x0 += 32) {
        #pragma unroll
        for (int l = 0; l < 4; l++) {
            int e = t + l * 128;
            ((float4*)Gr)[e] = ((const float4*)(G1r + (size_t)x0 * 64))[e];
            ((float4*)Gi)[e] = ((const float4*)(G1i + (size_t)x0 * 64))[e];
        }
        #pragma unroll
        for (int l = 0; l < 6; l++) {
            int e = t + l * 128;
            ((float4*)Fxs)[e] = ((const float4*)(g_FxB + (size_t)x0 * 96))[e];
        }
        __syncthreads();
        #pragma unroll 4
        for (int xx = 0; xx < 32; xx++) {
            float4 cv = *(float4*)&Fxs[xx * 96 + j0];
            float4 sv = *(float4*)&Fxs[xx * 96 + 32 + j0];
            float4 sn = *(float4*)&Fxs[xx * 96 + 64 + j0];
            ulonglong2 grp = *(ulonglong2*)&Gr[xx * 64 + c0];
            ulonglong2 gip = *(ulonglong2*)&Gi[xx * 64 + c0];
            unsigned long long pc[4] = {f2pack(cv.x,cv.x), f2pack(cv.y,cv.y),
                                        f2pack(cv.z,cv.z), f2pack(cv.w,cv.w)};
            unsigned long long ps[4] = {f2pack(sv.x,sv.x), f2pack(sv.y,sv.y),
                                        f2pack(sv.z,sv.z), f2pack(sv.w,sv.w)};
            unsigned long long pn[4] = {f2pack(sn.x,sn.x), f2pack(sn.y,sn.y),
                                        f2pack(sn.z,sn.z), f2pack(sn.w,sn.w)};
            #pragma unroll
            for (int jj = 0; jj < 4; jj++) {
                ffma2(aR[jj][0], pc[jj], grp.x); ffma2(aR[jj][0], ps[jj], gip.x);
                ffma2(aR[jj][1], pc[jj], grp.y); ffma2(aR[jj][1], ps[jj], gip.y);
                ffma2(aI[jj][0], pc[jj], gip.x); ffma2(aI[jj][0], pn[jj], grp.x);
                ffma2(aI[jj][1], pc[jj], gip.y); ffma2(aI[jj][1], pn[jj], grp.y);
            }
        }
        __syncthreads();
    }
    const float sc = 1.0f / 256.0f;
    #pragma unroll
    for (int jj = 0; jj < 4; jj++) {
        int j = j0 + jj;
        int idx = ((b * KX + j) * MODES + ky) * CI + c0;
        float r0, r1, r2, r3, i0, i1, i2, i3;
        f2unpack(aR[jj][0], r0, r1); f2unpack(aR[jj][1], r2, r3);
        f2unpack(aI[jj][0], i0, i1); f2unpack(aI[jj][1], i2, i3);
        *(float4*)&g_Gre[idx] = make_float4(r0*sc, r1*sc, r2*sc, r3*sc);
        *(float4*)&g_Gim[idx] = make_float4(i0*sc, i1*sc, i2*sc, i3*sc);
    }
}

// ---------------- Stage C2: channel mixing with transposed weights ----------------
__global__ __launch_bounds__(256) void kC2() {
    int ky = blockIdx.x & 15, j = blockIdx.x >> 4;
    __shared__ float wr[64 * 64];
    __shared__ float wi[64 * 64];
    __shared__ float gr[8 * 64];
    __shared__ float gi[8 * 64];
    int t = threadIdx.x;
    int base = (j * 16 + ky) * 4096;
    #pragma unroll
    for (int l = 0; l < 4; l++) {
        int e = t + l * 256;
        ((float4*)wr)[e] = ((const float4*)(g_Wr + base))[e];
        ((float4*)wi)[e] = ((const float4*)(g_Wi + base))[e];
    }
    #pragma unroll
    for (int l = 0; l < 2; l++) {
        int e = t + l * 256;
        int b = e >> 6, i = e & 63;
        int gidx = ((b * KX + j) * MODES + ky) * CI + i;
        gr[e] = g_Gre[gidx];
        gi[e] = g_Gim[gidx];
    }
    __syncthreads();
    #pragma unroll
    for (int l = 0; l < 2; l++) {
        int p = t + l * 256;
        int b = p >> 6, o = p & 63;
        float hr = 0.f, hi = 0.f;
        #pragma unroll 8
        for (int i = 0; i < 64; i++) {
            float ar = gr[b * 64 + i], ai = gi[b * 64 + i];
            float br = wr[i * 64 + o], bi = wi[i * 64 + o];
            hr += ar * br - ai * bi;
            hi += ar * bi + ai * br;
        }
        int hidx = ((b * CO + o) * KX + j) * MODES + ky;
        g_Hre[hidx] = hr;
        g_Him[hidx] = hi;
    }
}

// ---------------- Stage D: inverse x-DFT, layout [b][x][ky][o] ----------------
__global__ __launch_bounds__(256) void kD() {
    int o = blockIdx.x & 63, b = blockIdx.x >> 6;
    __shared__ __align__(16) float hr[KX * MODES];
    __shared__ __align__(16) float hi[KX * MODES];
    int t = threadIdx.x;
    int base = (b * CO + o) * KX * MODES;
    hr[t]       = g_Hre[base + t];
    hi[t]       = g_Him[base + t];
    hr[t + 256] = g_Hre[base + t + 256];
    hi[t + 256] = g_Him[base + t + 256];
    __syncthreads();
    int x = t;
    float vr[16] = {}, vi[16] = {};
    for (int j = 0; j < 32; j++) {
        float c =  g_Fx[j * 256 + x];
        float s = -g_Fx[(32 + j) * 256 + x];
        #pragma unroll
        for (int kv = 0; kv < 4; kv++) {
            float4 ar = *(float4*)&hr[j * 16 + kv * 4];
            float4 ai = *(float4*)&hi[j * 16 + kv * 4];
            vr[kv*4+0] += ar.x * c - ai.x * s;  vi[kv*4+0] += ar.x * s + ai.x * c;
            vr[kv*4+1] += ar.y * c - ai.y * s;  vi[kv*4+1] += ar.y * s + ai.y * c;
            vr[kv*4+2] += ar.z * c - ai.z * s;  vi[kv*4+2] += ar.z * s + ai.z * c;
            vr[kv*4+3] += ar.w * c - ai.w * s;  vi[kv*4+3] += ar.w * s + ai.w * c;
        }
    }
    const float sc = 1.0f / 256.0f;
    size_t vbase = ((size_t)(b * 256 + x)) * 16 * 64 + o;
    #pragma unroll
    for (int ky = 0; ky < 16; ky++) {
        g_Vre[vbase + ky * 64] = vr[ky] * sc;
        g_Vim[vbase + ky * 64] = vi[ky] * sc;
    }
}

// ---------------- Stage E: unified K=96 GEMM via mma.sync tf32 (3xTF32) ----------------
#define KE_ASTRIDE 100
#define KE_BSTRIDE 72
__global__ __launch_bounds__(256) void kE(const float* __restrict__ X,
                                          const float* __restrict__ Wres,
                                          const float* __restrict__ bres,
                                          float* __restrict__ out) {
    extern __shared__ float sm[];
    float* Ah = sm;                          // [128][100]
    float* Al = Ah + 128 * KE_ASTRIDE;
    float* Bh = Al + 128 * KE_ASTRIDE;       // [96][72]
    float* Bl = Bh + 96 * KE_BSTRIDE;
    float* bias = Bl + 96 * KE_BSTRIDE;      // [64]

    int bi = blockIdx.x;
    int b = bi >> 8, x = bi & 255;
    int t = threadIdx.x;
    int w = t >> 5, lane = t & 31, g = lane >> 2, tg = lane & 3;

    // ---- B fill (once) ----
    #pragma unroll
    for (int l = 0; l < 16; l++) {
        int e = t + l * 256;                 // 0..4095
        int k = e >> 6, o = e & 63;
        float v = Wres[e];
        float h = tf32f(v);
        Bh[k * KE_BSTRIDE + o] = h;
        Bl[k * KE_BSTRIDE + o] = tf32f(v - h);
    }
    {
        size_t vb = ((size_t)(b * 256 + x)) * 1024;
        #pragma unroll
        for (int l = 0; l < 8; l++) {
            int e = t + l * 256;             // 0..2047
            int kk = e >> 6, o = e & 63;
            float v = (kk < 16) ? g_Vre[vb + kk * 64 + o]
                                : g_Vim[vb + (kk - 16) * 64 + o];
            float h = tf32f(v);
            int r = (64 + kk) * KE_BSTRIDE + o;
            Bh[r] = h;
            Bl[r] = tf32f(v - h);
        }
    }
    if (t < 64) bias[t] = bres[t];

    const float* Xrow = X   + ((size_t)(b * 256 + x)) * 16384;
    float*       orow = out + ((size_t)(b * 256 + x)) * 16384;
    const uint32_t* Ahp = (const uint32_t*)Ah;
    const uint32_t* Alp = (const uint32_t*)Al;
    const uint32_t* Bhp = (const uint32_t*)Bh;
    const uint32_t* Blp = (const uint32_t*)Bl;

    for (int ch = 0; ch < 2; ch++) {
        int y0 = ch * 128;
        __syncthreads();
        // ---- A fill: X part (cols 0..63) ----
        #pragma unroll
        for (int l = 0; l < 8; l++) {
            int e = t + l * 256;             // f4 id 0..2047
            int yy = e >> 4, k4 = (e & 15) * 4;
            float4 v = *(const float4*)&Xrow[(size_t)(y0 + yy) * 64 + k4];
            int r = yy * KE_ASTRIDE + k4;
            float h;
            h = tf32f(v.x); Ah[r]     = h; Al[r]     = tf32f(v.x - h);
            h = tf32f(v.y); Ah[r + 1] = h; Al[r + 1] = tf32f(v.y - h);
            h = tf32f(v.z); Ah[r + 2] = h; Al[r + 2] = tf32f(v.z - h);
            h = tf32f(v.w); Ah[r + 3] = h; Al[r + 3] = tf32f(v.w - h);
        }
        // ---- A fill: WyE part (cols 64..95) ----
        #pragma unroll
        for (int l = 0; l < 16; l++) {
            int e = t + l * 256;             // 0..4095
            int kk = e >> 7, yy = e & 127;
            float v = g_WyE[kk * 256 + y0 + yy];
            float h = tf32f(v);
            int r = yy * KE_ASTRIDE + 64 + kk;
            Ah[r] = h;
            Al[r] = tf32f(v - h);
        }
        __syncthreads();

        float c0[8], c1[8], c2[8], c3[8];
        #pragma unroll
        for (int n = 0; n < 8; n++) { c0[n] = c1[n] = c2[n] = c3[n] = 0.f; }

        int ra = (w * 16 + g) * KE_ASTRIDE;
        #pragma unroll
        for (int k0 = 0; k0 < 96; k0 += 8) {
            uint32_t ah0 = Ahp[ra + k0 + tg];
            uint32_t ah1 = Ahp[ra + 8 * KE_ASTRIDE + k0 + tg];
            uint32_t ah2 = Ahp[ra + k0 + tg + 4];
            uint32_t ah3 = Ahp[ra + 8 * KE_ASTRIDE + k0 + tg + 4];
            uint32_t al0 = Alp[ra + k0 + tg];
            uint32_t al1 = Alp[ra + 8 * KE_ASTRIDE + k0 + tg];
            uint32_t al2 = Alp[ra + k0 + tg + 4];
            uint32_t al3 = Alp[ra + 8 * KE_ASTRIDE + k0 + tg + 4];
            int rb0 = (k0 + tg) * KE_BSTRIDE + g;
            int rb1 = (k0 + tg + 4) * KE_BSTRIDE + g;
            #pragma unroll
            for (int nt = 0; nt < 8; nt++) {
                uint32_t bh0 = Bhp[rb0 + nt * 8];
                uint32_t bh1 = Bhp[rb1 + nt * 8];
                uint32_t bl0 = Blp[rb0 + nt * 8];
                uint32_t bl1 = Blp[rb1 + nt * 8];
                mma_tf32(c0[nt], c1[nt], c2[nt], c3[nt], ah0, ah1, ah2, ah3, bh0, bh1);
                mma_tf32(c0[nt], c1[nt], c2[nt], c3[nt], ah0, ah1, ah2, ah3, bl0, bl1);
                mma_tf32(c0[nt], c1[nt], c2[nt], c3[nt], al0, al1, al2, al3, bh0, bh1);
            }
        }
        // ---- epilogue ----
        int row0 = y0 + w * 16 + g;
        int row1 = row0 + 8;
        #pragma unroll
        for (int nt = 0; nt < 8; nt++) {
            int col = nt * 8 + 2 * tg;
            float b0v = bias[col], b1v = bias[col + 1];
            float z0 = c0[nt] + b0v, z1 = c1[nt] + b1v;
            float z2 = c2[nt] + b0v, z3 = c3[nt] + b1v;
            z0 = z0 / (1.0f + __expf(-z0));
            z1 = z1 / (1.0f + __expf(-z1));
            z2 = z2 / (1.0f + __expf(-z2));
            z3 = z3 / (1.0f + __expf(-z3));
            float2 p0 = make_float2(z0, z1);
            float2 p1 = make_float2(z2, z3);
            *(float2*)&orow[(size_t)row0 * 64 + col] = p0;
            *(float2*)&orow[(size_t)row1 * 64 + col] = p1;
        }
    }
}

// ---------------- launch ----------------
extern "C" void kernel_launch(void* const* d_in, const int* in_sizes, int n_in,
                              void* d_out, int out_size) {
    const float* X    = (const float*)d_in[0];
    const float* Wres = (const float*)d_in[1];
    const float* bres = (const float*)d_in[2];
    const float* fw0  = (const float*)d_in[3];
    const float* fw1  = (const float*)d_in[4];
    float* out = (float*)d_out;

    const int kE_smem = (2 * 128 * KE_ASTRIDE + 2 * 96 * KE_BSTRIDE + 64) * 4;
    cudaFuncSetAttribute(kE, cudaFuncAttributeMaxDynamicSharedMemorySize, kE_smem);

    init_tables<<<96, 256>>>();
    kW<<<512, 256>>>(fw0, fw1);
    kA2<<<dim3(64, NB), 256>>>(X);
    kB2<<<128, 128>>>();
    kC2<<<KX * MODES, 256>>>();
    kD<<<NB * CO, 256>>>();
    kE<<<NB * RR, 256, kE_smem>>>(X, Wres, bres, out);
}

// round 7
// speedup vs baseline: 1.5320x; 1.2100x over previous
#include <cuda_runtime.h>
#include <math.h>
#include <stdint.h>

#define NB 8
#define RR 256
#define CI 64
#define CO 64
#define MODES 16
#define KX 32
#define GSZ (NB * KX * MODES * CI)   // 262144

// ---------------- f32x2 helpers ----------------
__device__ __forceinline__ unsigned long long f2pack(float a, float b) {
    unsigned long long r;
    asm("mov.b64 %0, {%1, %2};" : "=l"(r) : "f"(a), "f"(b));
    return r;
}
__device__ __forceinline__ void f2unpack(unsigned long long v, float& a, float& b) {
    asm("mov.b64 {%0, %1}, %2;" : "=f"(a), "=f"(b) : "l"(v));
}
__device__ __forceinline__ void ffma2(unsigned long long& d, unsigned long long a,
                                      unsigned long long b) {
    asm("fma.rn.f32x2 %0, %1, %2, %3;" : "=l"(d) : "l"(a), "l"(b), "l"(d));
}

// ---------------- tf32 helpers ----------------
__device__ __forceinline__ float tf32f(float f) {
    uint32_t r;
    asm("cvt.rna.tf32.f32 %0, %1;" : "=r"(r) : "f"(f));
    return __uint_as_float(r);
}
__device__ __forceinline__ void mma_tf32(float& c0, float& c1, float& c2, float& c3,
                                         uint32_t a0, uint32_t a1, uint32_t a2, uint32_t a3,
                                         uint32_t b0, uint32_t b1) {
    asm("mma.sync.aligned.m16n8k8.row.col.f32.tf32.tf32.f32 "
        "{%0,%1,%2,%3}, {%4,%5,%6,%7}, {%8,%9}, {%0,%1,%2,%3};"
        : "+f"(c0), "+f"(c1), "+f"(c2), "+f"(c3)
        : "r"(a0), "r"(a1), "r"(a2), "r"(a3), "r"(b0), "r"(b1));
}

// ---------------- device scratch ----------------
__device__ __align__(16) float g_Fx [64 * 256];       // [m][x] m<32:cos m>=32:-sin (kD)
__device__ __align__(16) float g_FxB[256 * 96];       // [x][m'] (kB2)
__device__ __align__(16) float g_Wy2[256 * 32];       // [y][kk] (kA2)
__device__ __align__(16) float g_WyE[32 * 256];       // [k'][y] (kE)
__device__ __align__(16) float g_T   [2 * 2097152];   // G1re | G1im : [b][ky][x][c]
__device__ __align__(16) float g_GreP[2 * GSZ];       // x-half partials
__device__ __align__(16) float g_GimP[2 * GSZ];
__device__ __align__(16) float g_Hre[NB * CO * KX * MODES];
__device__ __align__(16) float g_Him[NB * CO * KX * MODES];
__device__ __align__(16) float g_Vre[NB * RR * MODES * CO];  // [b][x][ky][o]
__device__ __align__(16) float g_Vim[NB * RR * MODES * CO];

// ---------------- table init ----------------
__global__ void init_tables() {
    int t = blockIdx.x * blockDim.x + threadIdx.x;   // < 24576
    if (t < 64 * 256) {                               // g_Fx
        int m = t >> 8, x = t & 255;
        int j = m & 31;
        int kx = (j < 16) ? j : (224 + j);
        float s, c;
        sincospif((float)((kx * x) & 255) * (1.0f / 128.0f), &s, &c);
        g_Fx[t] = (m < 32) ? c : -s;
    }
    if (t < 256 * 96) {                               // g_FxB
        int x = t / 96, m = t % 96;
        int j = m & 31;
        int kx = (j < 16) ? j : (224 + j);
        float s, c;
        sincospif((float)((kx * x) & 255) * (1.0f / 128.0f), &s, &c);
        g_FxB[t] = (m < 32) ? c : ((m < 64) ? s : -s);
    }
    if (t < 256 * 32) {                               // g_Wy2
        int y = t >> 5, kk = t & 31;
        int ky = kk & 15;
        float s, c;
        sincospif((float)((ky * y) & 255) * (1.0f / 128.0f), &s, &c);
        g_Wy2[t] = (kk < 16) ? c : -s;
    }
    if (t < 32 * 256) {                               // g_WyE
        int kk = t >> 8, y = t & 255;
        int ky = kk & 15;
        float f = (ky == 0) ? 1.0f : 2.0f;
        float s, c;
        sincospif((float)((ky * y) & 255) * (1.0f / 128.0f), &s, &c);
        g_WyE[t] = (kk < 16) ? f * c : -f * s;
    }
}

// ---------------- Stage A': y-direction partial DFT ----------------
__global__ __launch_bounds__(256) void kA2(const float* __restrict__ X) {
    int b  = blockIdx.y;
    int x0 = blockIdx.x * 4;
    __shared__ __align__(16) float Xs[4][32][64];
    __shared__ __align__(16) float Wys[32][32];
    int t  = threadIdx.x;
    int xl = t >> 6;
    int tt = t & 63;
    int kg = tt >> 3;
    int cg = tt & 7;
    int kk0 = kg * 4, c0 = cg * 8;

    unsigned long long acc[4][4];
    #pragma unroll
    for (int i = 0; i < 4; i++)
        #pragma unroll
        for (int p = 0; p < 4; p++) acc[i][p] = 0ull;

    for (int ych = 0; ych < 8; ych++) {
        int y0 = ych * 32;
        #pragma unroll
        for (int l = 0; l < 8; l++) {
            int e = t + l * 256;
            int c4 = e & 15, yy = (e >> 4) & 31, xs = e >> 9;
            *(float4*)&Xs[xs][yy][c4 * 4] =
                *(const float4*)&X[((size_t)((b * 256 + x0 + xs)) * 256 + y0 + yy) * 64 + c4 * 4];
        }
        {
            int kk4 = t & 7, yy = t >> 3;
            *(float4*)&Wys[yy][kk4 * 4] = *(const float4*)&g_Wy2[(y0 + yy) * 32 + kk4 * 4];
        }
        __syncthreads();
        #pragma unroll 8
        for (int yy = 0; yy < 32; yy++) {
            float4 a4 = *(float4*)&Wys[yy][kk0];
            unsigned long long pa0 = f2pack(a4.x, a4.x);
            unsigned long long pa1 = f2pack(a4.y, a4.y);
            unsigned long long pa2 = f2pack(a4.z, a4.z);
            unsigned long long pa3 = f2pack(a4.w, a4.w);
            ulonglong2 b01 = *(ulonglong2*)&Xs[xl][yy][c0];
            ulonglong2 b23 = *(ulonglong2*)&Xs[xl][yy][c0 + 4];
            ffma2(acc[0][0], pa0, b01.x); ffma2(acc[0][1], pa0, b01.y);
            ffma2(acc[0][2], pa0, b23.x); ffma2(acc[0][3], pa0, b23.y);
            ffma2(acc[1][0], pa1, b01.x); ffma2(acc[1][1], pa1, b01.y);
            ffma2(acc[1][2], pa1, b23.x); ffma2(acc[1][3], pa1, b23.y);
            ffma2(acc[2][0], pa2, b01.x); ffma2(acc[2][1], pa2, b01.y);
            ffma2(acc[2][2], pa2, b23.x); ffma2(acc[2][3], pa2, b23.y);
            ffma2(acc[3][0], pa3, b01.x); ffma2(acc[3][1], pa3, b01.y);
            ffma2(acc[3][2], pa3, b23.x); ffma2(acc[3][3], pa3, b23.y);
        }
        __syncthreads();
    }
    int x = x0 + xl;
    #pragma unroll
    for (int j = 0; j < 4; j++) {
        int kk = kk0 + j;
        int ky = kk & 15;
        float* dst = (kk < 16 ? g_T : g_T + 2097152) +
                     ((size_t)((b * 16 + ky) * 256 + x)) * 64 + c0;
        float v[8];
        #pragma unroll
        for (int p = 0; p < 4; p++) f2unpack(acc[j][p], v[2 * p], v[2 * p + 1]);
        *(float4*)&dst[0] = make_float4(v[0], v[1], v[2], v[3]);
        *(float4*)&dst[4] = make_float4(v[4], v[5], v[6], v[7]);
    }
}

// ---------------- Stage B': x-direction partial DFT (x-split halves) ----------------
__global__ __launch_bounds__(128) void kB2() {
    int b = blockIdx.x >> 4, ky = blockIdx.x & 15;
    int xh = blockIdx.y;
    __shared__ __align__(16) float Gr[32 * 64];
    __shared__ __align__(16) float Gi[32 * 64];
    __shared__ __align__(16) float Fxs[32 * 96];
    int t = threadIdx.x;
    int jg = t >> 4, cg = t & 15;
    int j0 = jg * 4, c0 = cg * 4;

    const float* G1r = g_T + ((size_t)(b * 16 + ky)) * 256 * 64;
    const float* G1i = g_T + 2097152 + ((size_t)(b * 16 + ky)) * 256 * 64;

    unsigned long long aR[4][2], aI[4][2];
    #pragma unroll
    for (int i = 0; i < 4; i++) { aR[i][0]=aR[i][1]=aI[i][0]=aI[i][1]=0ull; }

    int xbeg = xh * 128;
    for (int x0 = xbeg; x0 < xbeg + 128; x0 += 32) {
        #pragma unroll
        for (int l = 0; l < 4; l++) {
            int e = t + l * 128;
            ((float4*)Gr)[e] = ((const float4*)(G1r + (size_t)x0 * 64))[e];
            ((float4*)Gi)[e] = ((const float4*)(G1i + (size_t)x0 * 64))[e];
        }
        #pragma unroll
        for (int l = 0; l < 6; l++) {
            int e = t + l * 128;
            ((float4*)Fxs)[e] = ((const float4*)(g_FxB + (size_t)x0 * 96))[e];
        }
        __syncthreads();
        #pragma unroll 4
        for (int xx = 0; xx < 32; xx++) {
            float4 cv = *(float4*)&Fxs[xx * 96 + j0];
            float4 sv = *(float4*)&Fxs[xx * 96 + 32 + j0];
            float4 sn = *(float4*)&Fxs[xx * 96 + 64 + j0];
            ulonglong2 grp = *(ulonglong2*)&Gr[xx * 64 + c0];
            ulonglong2 gip = *(ulonglong2*)&Gi[xx * 64 + c0];
            unsigned long long pc[4] = {f2pack(cv.x,cv.x), f2pack(cv.y,cv.y),
                                        f2pack(cv.z,cv.z), f2pack(cv.w,cv.w)};
            unsigned long long ps[4] = {f2pack(sv.x,sv.x), f2pack(sv.y,sv.y),
                                        f2pack(sv.z,sv.z), f2pack(sv.w,sv.w)};
            unsigned long long pn[4] = {f2pack(sn.x,sn.x), f2pack(sn.y,sn.y),
                                        f2pack(sn.z,sn.z), f2pack(sn.w,sn.w)};
            #pragma unroll
            for (int jj = 0; jj < 4; jj++) {
                ffma2(aR[jj][0], pc[jj], grp.x); ffma2(aR[jj][0], ps[jj], gip.x);
                ffma2(aR[jj][1], pc[jj], grp.y); ffma2(aR[jj][1], ps[jj], gip.y);
                ffma2(aI[jj][0], pc[jj], gip.x); ffma2(aI[jj][0], pn[jj], grp.x);
                ffma2(aI[jj][1], pc[jj], gip.y); ffma2(aI[jj][1], pn[jj], grp.y);
            }
        }
        __syncthreads();
    }
    const float sc = 1.0f / 256.0f;
    float* dstR = g_GreP + (size_t)xh * GSZ;
    float* dstI = g_GimP + (size_t)xh * GSZ;
    #pragma unroll
    for (int jj = 0; jj < 4; jj++) {
        int j = j0 + jj;
        int idx = ((b * KX + j) * MODES + ky) * CI + c0;
        float r0, r1, r2, r3, i0, i1, i2, i3;
        f2unpack(aR[jj][0], r0, r1); f2unpack(aR[jj][1], r2, r3);
        f2unpack(aI[jj][0], i0, i1); f2unpack(aI[jj][1], i2, i3);
        *(float4*)&dstR[idx] = make_float4(r0*sc, r1*sc, r2*sc, r3*sc);
        *(float4*)&dstI[idx] = make_float4(i0*sc, i1*sc, i2*sc, i3*sc);
    }
}

// ---------------- Stage C3: channel mixing, direct fw reads ----------------
// grid 128 = j(32) x bpair(4); block 256 = o(64) x kyg(4)
// H[b][o][j][ky] = sum_i G[b][i] * w[i][o]
__global__ __launch_bounds__(256) void kC3(const float* __restrict__ fw0,
                                           const float* __restrict__ fw1) {
    __shared__ __align__(16) float ws[512 * 36];   // [(i*64+o)][36] rows of 32+pad
    __shared__ __align__(16) float Gsr[16 * 16];   // [ky][i*2+b]
    __shared__ __align__(16) float Gsi[16 * 16];
    int bx = blockIdx.x;
    int j = bx >> 2, bp = bx & 3;
    const float* fw = (j < 16) ? fw0 : fw1;
    int jm = j & 15;
    int t = threadIdx.x;
    int o = t & 63, kyg = t >> 6;

    float accR[2][4] = {}, accI[2][4] = {};

    for (int i0 = 0; i0 < 64; i0 += 8) {
        __syncthreads();
        // load weights: 512 rows (i local 8 x o 64), 32 floats each, pitch 36
        #pragma unroll
        for (int l = 0; l < 16; l++) {
            int r = l * 32 + (t >> 3);
            int col = t & 7;
            int il = r >> 6, oo = r & 63;
            float4 v = *(const float4*)&fw[(((size_t)((i0 + il) * 64 + oo) * 16 + jm) * 32) + col * 4];
            *(float4*)&ws[r * 36 + col * 4] = v;
        }
        // load G chunk (sum both x-halves)
        #pragma unroll
        for (int l = 0; l < 2; l++) {
            int e = t;                       // 256 items per target
            int b = e & 1, il = (e >> 1) & 7, ky = e >> 4;
            int bg = bp * 2 + b;
            int gidx = ((bg * KX + j) * MODES + ky) * CI + i0 + il;
            if (l == 0) Gsr[ky * 16 + il * 2 + b] = g_GreP[gidx] + g_GreP[GSZ + gidx];
            else        Gsi[ky * 16 + il * 2 + b] = g_GimP[gidx] + g_GimP[GSZ + gidx];
        }
        __syncthreads();
        #pragma unroll
        for (int il = 0; il < 8; il++) {
            float4 f4a = *(float4*)&ws[(il * 64 + o) * 36 + kyg * 8];
            float4 f4b = *(float4*)&ws[(il * 64 + o) * 36 + kyg * 8 + 4];
            float wr[4] = {f4a.x, f4a.z, f4b.x, f4b.z};
            float wi[4] = {f4a.y, f4a.w, f4b.y, f4b.w};
            #pragma unroll
            for (int b = 0; b < 2; b++) {
                #pragma unroll
                for (int q = 0; q < 4; q++) {
                    int ky = kyg * 4 + q;
                    float gr = Gsr[ky * 16 + il * 2 + b];
                    float gi = Gsi[ky * 16 + il * 2 + b];
                    accR[b][q] += gr * wr[q] - gi * wi[q];
                    accI[b][q] += gr * wi[q] + gi * wr[q];
                }
            }
        }
    }
    #pragma unroll
    for (int b = 0; b < 2; b++) {
        int bg = bp * 2 + b;
        int hidx = ((bg * CO + o) * KX + j) * MODES + kyg * 4;
        *(float4*)&g_Hre[hidx] = make_float4(accR[b][0], accR[b][1], accR[b][2], accR[b][3]);
        *(float4*)&g_Him[hidx] = make_float4(accI[b][0], accI[b][1], accI[b][2], accI[b][3]);
    }
}

// ---------------- Stage D: inverse x-DFT, layout [b][x][ky][o] ----------------
__global__ __launch_bounds__(256) void kD() {
    int o = blockIdx.x & 63, b = blockIdx.x >> 6;
    __shared__ __align__(16) float hr[KX * MODES];
    __shared__ __align__(16) float hi[KX * MODES];
    int t = threadIdx.x;
    int base = (b * CO + o) * KX * MODES;
    hr[t]       = g_Hre[base + t];
    hi[t]       = g_Him[base + t];
    hr[t + 256] = g_Hre[base + t + 256];
    hi[t + 256] = g_Him[base + t + 256];
    __syncthreads();
    int x = t;
    float vr[16] = {}, vi[16] = {};
    for (int j = 0; j < 32; j++) {
        float c =  g_Fx[j * 256 + x];
        float s = -g_Fx[(32 + j) * 256 + x];
        #pragma unroll
        for (int kv = 0; kv < 4; kv++) {
            float4 ar = *(float4*)&hr[j * 16 + kv * 4];
            float4 ai = *(float4*)&hi[j * 16 + kv * 4];
            vr[kv*4+0] += ar.x * c - ai.x * s;  vi[kv*4+0] += ar.x * s + ai.x * c;
            vr[kv*4+1] += ar.y * c - ai.y * s;  vi[kv*4+1] += ar.y * s + ai.y * c;
            vr[kv*4+2] += ar.z * c - ai.z * s;  vi[kv*4+2] += ar.z * s + ai.z * c;
            vr[kv*4+3] += ar.w * c - ai.w * s;  vi[kv*4+3] += ar.w * s + ai.w * c;
        }
    }
    const float sc = 1.0f / 256.0f;
    size_t vbase = ((size_t)(b * 256 + x)) * 16 * 64 + o;
    #pragma unroll
    for (int ky = 0; ky < 16; ky++) {
        g_Vre[vbase + ky * 64] = vr[ky] * sc;
        g_Vim[vbase + ky * 64] = vi[ky] * sc;
    }
}

// ---------------- Stage E: unified K=96 GEMM, 64-row chunks, high occupancy ----------------
#define KE_ASTRIDE 100
#define KE_BSTRIDE 72
__global__ __launch_bounds__(256) void kE(const float* __restrict__ X,
                                          const float* __restrict__ Wres,
                                          const float* __restrict__ bres,
                                          float* __restrict__ out) {
    extern __shared__ float sm[];
    float* Ah = sm;                          // [64][100]
    float* Al = Ah + 64 * KE_ASTRIDE;
    float* Bh = Al + 64 * KE_ASTRIDE;        // [96][72]
    float* Bl = Bh + 96 * KE_BSTRIDE;
    float* bias = Bl + 96 * KE_BSTRIDE;      // [64]

    int bi = blockIdx.x;
    int b = bi >> 8, x = bi & 255;
    int t = threadIdx.x;
    int w = t >> 5, lane = t & 31, g = lane >> 2, tg = lane & 3;
    int mt = w & 3, nh = w >> 2;             // 4 m-tiles x 2 n-halves

    // ---- B fill (once) ----
    #pragma unroll
    for (int l = 0; l < 16; l++) {
        int e = t + l * 256;                 // 0..4095
        int k = e >> 6, o = e & 63;
        float v = Wres[e];
        float h = tf32f(v);
        Bh[k * KE_BSTRIDE + o] = h;
        Bl[k * KE_BSTRIDE + o] = tf32f(v - h);
    }
    {
        size_t vb = ((size_t)(b * 256 + x)) * 1024;
        #pragma unroll
        for (int l = 0; l < 8; l++) {
            int e = t + l * 256;             // 0..2047
            int kk = e >> 6, o = e & 63;
            float v = (kk < 16) ? g_Vre[vb + kk * 64 + o]
                                : g_Vim[vb + (kk - 16) * 64 + o];
            float h = tf32f(v);
            int r = (64 + kk) * KE_BSTRIDE + o;
            Bh[r] = h;
            Bl[r] = tf32f(v - h);
        }
    }
    if (t < 64) bias[t] = bres[t];

    const float* Xrow = X   + ((size_t)(b * 256 + x)) * 16384;
    float*       orow = out + ((size_t)(b * 256 + x)) * 16384;
    const uint32_t* Ahp = (const uint32_t*)Ah;
    const uint32_t* Alp = (const uint32_t*)Al;
    const uint32_t* Bhp = (const uint32_t*)Bh;
    const uint32_t* Blp = (const uint32_t*)Bl;

    for (int ch = 0; ch < 4; ch++) {
        int y0 = ch * 64;
        __syncthreads();
        // ---- A fill: X part (cols 0..63), 64 rows ----
        #pragma unroll
        for (int l = 0; l < 4; l++) {
            int e = t + l * 256;             // f4 id 0..1023
            int yy = e >> 4, k4 = (e & 15) * 4;
            float4 v = *(const float4*)&Xrow[(size_t)(y0 + yy) * 64 + k4];
            int r = yy * KE_ASTRIDE + k4;
            float h;
            h = tf32f(v.x); Ah[r]     = h; Al[r]     = tf32f(v.x - h);
            h = tf32f(v.y); Ah[r + 1] = h; Al[r + 1] = tf32f(v.y - h);
            h = tf32f(v.z); Ah[r + 2] = h; Al[r + 2] = tf32f(v.z - h);
            h = tf32f(v.w); Ah[r + 3] = h; Al[r + 3] = tf32f(v.w - h);
        }
        // ---- A fill: WyE part (cols 64..95) ----
        #pragma unroll
        for (int l = 0; l < 8; l++) {
            int e = t + l * 256;             // 0..2047
            int kk = e >> 6, yy = e & 63;
            float v = g_WyE[kk * 256 + y0 + yy];
            float h = tf32f(v);
            int r = yy * KE_ASTRIDE + 64 + kk;
            Ah[r] = h;
            Al[r] = tf32f(v - h);
        }
        __syncthreads();

        float c0[4], c1[4], c2[4], c3[4];
        #pragma unroll
        for (int n = 0; n < 4; n++) { c0[n] = c1[n] = c2[n] = c3[n] = 0.f; }

        int ra = (mt * 16 + g) * KE_ASTRIDE;
        #pragma unroll
        for (int k0 = 0; k0 < 96; k0 += 8) {
            uint32_t ah0 = Ahp[ra + k0 + tg];
            uint32_t ah1 = Ahp[ra + 8 * KE_ASTRIDE + k0 + tg];
            uint32_t ah2 = Ahp[ra + k0 + tg + 4];
            uint32_t ah3 = Ahp[ra + 8 * KE_ASTRIDE + k0 + tg + 4];
            uint32_t al0 = Alp[ra + k0 + tg];
            uint32_t al1 = Alp[ra + 8 * KE_ASTRIDE + k0 + tg];
            uint32_t al2 = Alp[ra + k0 + tg + 4];
            uint32_t al3 = Alp[ra + 8 * KE_ASTRIDE + k0 + tg + 4];
            int rb0 = (k0 + tg) * KE_BSTRIDE + g;
            int rb1 = (k0 + tg + 4) * KE_BSTRIDE + g;
            #pragma unroll
            for (int nl = 0; nl < 4; nl++) {
                int nt = nh * 4 + nl;
                uint32_t bh0 = Bhp[rb0 + nt * 8];
                uint32_t bh1 = Bhp[rb1 + nt * 8];
                uint32_t bl0 = Blp[rb0 + nt * 8];
                uint32_t bl1 = Blp[rb1 + nt * 8];
                mma_tf32(c0[nl], c1[nl], c2[nl], c3[nl], ah0, ah1, ah2, ah3, bh0, bh1);
                mma_tf32(c0[nl], c1[nl], c2[nl], c3[nl], ah0, ah1, ah2, ah3, bl0, bl1);
                mma_tf32(c0[nl], c1[nl], c2[nl], c3[nl], al0, al1, al2, al3, bh0, bh1);
            }
        }
        // ---- epilogue ----
        int row0 = y0 + mt * 16 + g;
        int row1 = row0 + 8;
        #pragma unroll
        for (int nl = 0; nl < 4; nl++) {
            int col = (nh * 4 + nl) * 8 + 2 * tg;
            float b0v = bias[col], b1v = bias[col + 1];
            float z0 = c0[nl] + b0v, z1 = c1[nl] + b1v;
            float z2 = c2[nl] + b0v, z3 = c3[nl] + b1v;
            z0 = z0 / (1.0f + __expf(-z0));
            z1 = z1 / (1.0f + __expf(-z1));
            z2 = z2 / (1.0f + __expf(-z2));
            z3 = z3 / (1.0f + __expf(-z3));
            *(float2*)&orow[(size_t)row0 * 64 + col] = make_float2(z0, z1);
            *(float2*)&orow[(size_t)row1 * 64 + col] = make_float2(z2, z3);
        }
    }
}

// ---------------- launch ----------------
extern "C" void kernel_launch(void* const* d_in, const int* in_sizes, int n_in,
                              void* d_out, int out_size) {
    const float* X    = (const float*)d_in[0];
    const float* Wres = (const float*)d_in[1];
    const float* bres = (const float*)d_in[2];
    const float* fw0  = (const float*)d_in[3];
    const float* fw1  = (const float*)d_in[4];
    float* out = (float*)d_out;

    const int kE_smem = (2 * 64 * KE_ASTRIDE + 2 * 96 * KE_BSTRIDE + 64) * 4;
    cudaFuncSetAttribute(kE, cudaFuncAttributeMaxDynamicSharedMemorySize, kE_smem);

    init_tables<<<96, 256>>>();
    kA2<<<dim3(64, NB), 256>>>(X);
    kB2<<<dim3(128, 2), 128>>>();
    kC3<<<128, 256>>>(fw0, fw1);
    kD<<<NB * CO, 256>>>();
    kE<<<NB * RR, 256, kE_smem>>>(X, Wres, bres, out);
}